// round 11
// baseline (speedup 1.0000x reference)
#include <cuda_runtime.h>

// LSTM char-RNN, fused persistent kernel — R11: split-K, 512 threads/CTA.
//   inputs [1024,256] i32, Wx [128,1024] f32, R [256,1024] f32,
//   bias [1024] f32, dense_w [256,128] f32, dense_b [128] f32
//   out = softmax(h_T @ dense_w + dense_b) -> [1024,128] f32
//
// 128 CTAs x 512 threads. CTA owns 8 batch rows. Thread (u, half) = unit u,
// k-half half: accumulates z[4 gates][8 rows] over 128 k (16 f32x2 accs).
// After the K loop the halves exchange complement row-pairs via SMEM
// (transposed, conflict-free) and each thread runs the epilogue for 4 rows.
// 4 warps/SMSP (vs 2 in R9) to hide LDS/LDG/MUFU/barrier latency that was
// leaving the FMA pipe at 53%.

#define BATCHN   1024
#define SEQLEN   256
#define UNITSN   256
#define NCHARS   128
#define BT       8
#define NCTA     (BATCHN / BT)   // 128
#define NTHR     512
#define FOURU    (4 * UNITSN)    // 1024
#define KHALF    (UNITSN / 2)    // 128
#define NCHUNK   32              // chunks of 4 k per half

#define FMA2(acc, a, b) \
    asm("fma.rn.f32x2 %0, %1, %2, %0;" : "+l"(acc) : "l"(a), "l"(b))
#define ADD2(acc, b) \
    asm("add.rn.f32x2 %0, %0, %1;" : "+l"(acc) : "l"(b))

__device__ __forceinline__ unsigned long long bcast2(float v) {
    unsigned long long r;
    unsigned u = __float_as_uint(v);
    asm("mov.b64 %0, {%1, %1};" : "=l"(r) : "r"(u));
    return r;
}

__device__ __forceinline__ void unpack2(unsigned long long v, float& lo, float& hi) {
    unsigned a, b;
    asm("mov.b64 {%0, %1}, %2;" : "=r"(a), "=r"(b) : "l"(v));
    lo = __uint_as_float(a);
    hi = __uint_as_float(b);
}

// exp-based activations (~1e-6 rel err; tanh.approx's ~1e-3 would be amplified
// by the recurrence past the 1e-3 output threshold).
__device__ __forceinline__ float fast_sigmoid(float x) {
    return __fdividef(1.0f, 1.0f + __expf(-x));
}
__device__ __forceinline__ float fast_tanh(float x) {
    float e = __expf(2.0f * x);            // inf for large x -> 1, ok
    return 1.0f - __fdividef(2.0f, e + 1.0f);
}

// Stage 16 R values (4 k x 4 gates) for one chunk into registers.
__device__ __forceinline__ void load_chunk4(
    float (&buf)[16], const float* __restrict__ RbaseH, int kc)
{
    const float* p = RbaseH + kc * (4 * FOURU);
#pragma unroll
    for (int kk = 0; kk < 4; ++kk)
#pragma unroll
        for (int g = 0; g < 4; ++g)
            buf[kk * 4 + g] = p[kk * FOURU + g * UNITSN];
}

// 4 k of the recurrent GEMM: acc2[g][p] += h[k][2p,2p+1] * R[k][g*U+u].
__device__ __forceinline__ void compute_chunk4(
    unsigned long long (&acc2)[4][4],
    const float (&buf)[16],
    const float (*h_s)[BT],
    int k0)
{
#pragma unroll
    for (int kk = 0; kk < 4; ++kk) {
        const ulonglong2* hp = (const ulonglong2*)(&h_s[k0 + kk][0]);
        ulonglong2 pA = hp[0], pB = hp[1];
#pragma unroll
        for (int g = 0; g < 4; ++g) {
            unsigned long long rv = bcast2(buf[kk * 4 + g]);
            FMA2(acc2[g][0], pA.x, rv);
            FMA2(acc2[g][1], pA.y, rv);
            FMA2(acc2[g][2], pB.x, rv);
            FMA2(acc2[g][3], pB.y, rv);
        }
    }
}

__global__ void __launch_bounds__(NTHR, 1) lstm_fused_kernel(
    const int*   __restrict__ inp,
    const float* __restrict__ Wx,
    const float* __restrict__ R,
    const float* __restrict__ bias,
    const float* __restrict__ Wd,
    const float* __restrict__ bd,
    float*       __restrict__ out)
{
    __shared__ __align__(16) float h_s[UNITSN][BT];            // 8 KB
    __shared__ unsigned char idx_all[SEQLEN][BT];              // 2 KB
    __shared__ __align__(16) unsigned long long red_s[8][NTHR];// 32 KB, transposed

    const int tid  = threadIdx.x;
    const int u    = tid & (UNITSN - 1);   // unit 0..255
    const int half = tid >> 8;             // k-half 0/1
    const int b0   = blockIdx.x * BT;

    // Preload all step indices (values < 128 -> bytes).
    for (int i = tid; i < SEQLEN * BT; i += NTHR) {
        int r = i & (BT - 1);
        int t = i >> 3;
        idx_all[t][r] = (unsigned char)inp[(b0 + r) * SEQLEN + t];
    }
    for (int i = tid; i < UNITSN * BT; i += NTHR)
        ((float*)h_s)[i] = 0.0f;

    // This thread's 4 rows: [half*4, half*4+4). c state for those rows.
    float c_reg[4] = {0.f, 0.f, 0.f, 0.f};

    float bia[4];
#pragma unroll
    for (int g = 0; g < 4; ++g) bia[g] = bias[g * UNITSN + u];

    const float* RbaseH = R + u + (half * KHALF) * FOURU;
    const int    kbase  = half * KHALF;

    float ra[16], rb[16];
    load_chunk4(ra, RbaseH, 0);
    load_chunk4(rb, RbaseH, 1);

    const int peer  = tid ^ 256;
    const int pput  = 2 * (1 - half);   // pairs this thread ships to its peer
    const int pown  = 2 * half;         // pairs this thread keeps

    for (int t = 0; t < SEQLEN; ++t) {
        __syncthreads();   // h_s(t-1) visible; red_s(t-1) fully consumed

        unsigned long long acc2[4][4];
#pragma unroll
        for (int g = 0; g < 4; ++g)
#pragma unroll
            for (int p = 0; p < 4; ++p) acc2[g][p] = 0ull;

        // ---- K loop over this thread's 128 k, chunks of 4, rotate+wrap ----
        for (int kc = 0; kc < 16; kc += 2) {
            compute_chunk4(acc2, ra, h_s, kbase + kc * 4);
            load_chunk4(ra, RbaseH, (kc + 2) & (NCHUNK - 1));
            compute_chunk4(acc2, rb, h_s, kbase + (kc + 1) * 4);
            load_chunk4(rb, RbaseH, (kc + 3) & (NCHUNK - 1));
        }

        // Wx gather for this thread's 4 epilogue rows (consumed much later).
        float xf[4][4];
#pragma unroll
        for (int rr = 0; rr < 4; ++rr) {
            int ci = idx_all[t][half * 4 + rr];
            const float* wrow = Wx + ci * FOURU + u;
#pragma unroll
            for (int g = 0; g < 4; ++g)
                xf[g][rr] = wrow[g * UNITSN];
        }

        for (int kc = 16; kc < NCHUNK; kc += 2) {
            compute_chunk4(acc2, ra, h_s, kbase + kc * 4);
            load_chunk4(ra, RbaseH, (kc + 2) & (NCHUNK - 1));  // wraps to 0,1
            compute_chunk4(acc2, rb, h_s, kbase + (kc + 1) * 4);
            load_chunk4(rb, RbaseH, (kc + 3) & (NCHUNK - 1));
        }

        // ---- exchange complement row-pairs with the peer k-half ----
#pragma unroll
        for (int g = 0; g < 4; ++g)
#pragma unroll
            for (int q = 0; q < 2; ++q)
                red_s[g * 2 + q][peer] = acc2[g][pput + q];

        __syncthreads();   // partials visible; all h_s reads of step t done

#pragma unroll
        for (int g = 0; g < 4; ++g)
#pragma unroll
            for (int q = 0; q < 2; ++q)
                ADD2(acc2[g][pown + q], red_s[g * 2 + q][tid]);

        // ---- gates + state update for 4 rows ----
        float hv[4];
#pragma unroll
        for (int q = 0; q < 2; ++q) {
            float zi0, zi1, zf0, zf1, zg0, zg1, zo0, zo1;
            unpack2(acc2[0][pown + q], zi0, zi1);
            unpack2(acc2[1][pown + q], zf0, zf1);
            unpack2(acc2[2][pown + q], zg0, zg1);
            unpack2(acc2[3][pown + q], zo0, zo1);
            zi0 += bia[0] + xf[0][2 * q]; zi1 += bia[0] + xf[0][2 * q + 1];
            zf0 += bia[1] + xf[1][2 * q]; zf1 += bia[1] + xf[1][2 * q + 1];
            zg0 += bia[2] + xf[2][2 * q]; zg1 += bia[2] + xf[2][2 * q + 1];
            zo0 += bia[3] + xf[3][2 * q]; zo1 += bia[3] + xf[3][2 * q + 1];
            {
                float i = fast_sigmoid(zi0), f = fast_sigmoid(zf0);
                float g = fast_tanh(zg0),    o = fast_sigmoid(zo0);
                float c = f * c_reg[2 * q] + i * g;
                c_reg[2 * q] = c;
                hv[2 * q] = o * fast_tanh(c);
            }
            {
                float i = fast_sigmoid(zi1), f = fast_sigmoid(zf1);
                float g = fast_tanh(zg1),    o = fast_sigmoid(zo1);
                float c = f * c_reg[2 * q + 1] + i * g;
                c_reg[2 * q + 1] = c;
                hv[2 * q + 1] = o * fast_tanh(c);
            }
        }

        // write this thread's 4 h values (peer writes the other 4)
        *(float4*)(&h_s[u][half * 4]) = make_float4(hv[0], hv[1], hv[2], hv[3]);
    }
    __syncthreads();       // final h visible

    // ---- dense + softmax: warps 0..7 handle one batch row each ----
    const int w = tid >> 5;
    const int l = tid & 31;
    if (w < BT) {
        float4 bb = ((const float4*)bd)[l];
        float a0 = bb.x, a1 = bb.y, a2 = bb.z, a3 = bb.w;
#pragma unroll 4
        for (int uu = 0; uu < UNITSN; ++uu) {
            float hvv = h_s[uu][w];                                  // broadcast
            float4 wv = *(const float4*)(Wd + uu * NCHARS + 4 * l);  // coalesced
            a0 += hvv * wv.x; a1 += hvv * wv.y;
            a2 += hvv * wv.z; a3 += hvv * wv.w;
        }
        float m = fmaxf(fmaxf(a0, a1), fmaxf(a2, a3));
#pragma unroll
        for (int off = 16; off; off >>= 1)
            m = fmaxf(m, __shfl_xor_sync(0xffffffffu, m, off));
        float e0 = __expf(a0 - m), e1 = __expf(a1 - m);
        float e2 = __expf(a2 - m), e3 = __expf(a3 - m);
        float s = e0 + e1 + e2 + e3;
#pragma unroll
        for (int off = 16; off; off >>= 1)
            s += __shfl_xor_sync(0xffffffffu, s, off);
        float inv = 1.0f / s;
        *(float4*)(out + (b0 + w) * NCHARS + 4 * l) =
            make_float4(e0 * inv, e1 * inv, e2 * inv, e3 * inv);
    }
}

extern "C" void kernel_launch(void* const* d_in, const int* in_sizes, int n_in,
                              void* d_out, int out_size)
{
    const int*   inp  = (const int*)d_in[0];    // [1024, 256]
    const float* Wx   = (const float*)d_in[1];  // [128, 1024]
    const float* R    = (const float*)d_in[2];  // [256, 1024]
    const float* bias = (const float*)d_in[3];  // [1024]
    const float* Wd   = (const float*)d_in[4];  // [256, 128]
    const float* bd   = (const float*)d_in[5];  // [128]
    float*       out  = (float*)d_out;          // [1024, 128]

    lstm_fused_kernel<<<NCTA, NTHR>>>(inp, Wx, R, bias, Wd, bd, out);
}

// round 12
// speedup vs baseline: 1.0662x; 1.0662x over previous
#include <cuda_runtime.h>

// LSTM char-RNN — R12: R9 skeleton + gate-interleaved weights (LDG.128).
//   inputs [1024,256] i32, Wx [128,1024] f32, R [256,1024] f32,
//   bias [1024] f32, dense_w [256,128] f32, dense_b [128] f32
//   out = softmax(h_T @ dense_w + dense_b) -> [1024,128] f32
//
// Launch 1: permute R -> R_perm[k][u][g] and Wx -> Wx_perm[c][u][g] so the 4
// gate weights of unit u are one float4 (1 LDG.128/k instead of 4 LDG.32).
// Launch 2: fused LSTM. 128 CTAs x 256 thr; CTA owns 8 batch rows; thread owns
// unit u (4 gates x 8 rows = 16 f32x2 accs); h in SMEM, c in regs.

#define BATCHN   1024
#define SEQLEN   256
#define UNITSN   256
#define NCHARS   128
#define BT       8
#define NCTA     (BATCHN / BT)   // 128
#define NTHR     256
#define FOURU    (4 * UNITSN)    // 1024
#define NCHUNK   64              // chunks of 4 k

__device__ float R_perm[UNITSN * FOURU];    // [k][u][g], 1 MB
__device__ float Wx_perm[NCHARS * FOURU];   // [c][u][g], 512 KB

#define FMA2(acc, a, b) \
    asm("fma.rn.f32x2 %0, %1, %2, %0;" : "+l"(acc) : "l"(a), "l"(b))

__device__ __forceinline__ unsigned long long bcast2(float v) {
    unsigned long long r;
    unsigned u = __float_as_uint(v);
    asm("mov.b64 %0, {%1, %1};" : "=l"(r) : "r"(u));
    return r;
}

__device__ __forceinline__ void unpack2(unsigned long long v, float& lo, float& hi) {
    unsigned a, b;
    asm("mov.b64 {%0, %1}, %2;" : "=r"(a), "=r"(b) : "l"(v));
    lo = __uint_as_float(a);
    hi = __uint_as_float(b);
}

// exp-based activations (~1e-6 rel err; tanh.approx's ~1e-3 would be amplified
// by the recurrence past the 1e-3 output threshold).
__device__ __forceinline__ float fast_sigmoid(float x) {
    return __fdividef(1.0f, 1.0f + __expf(-x));
}
__device__ __forceinline__ float fast_tanh(float x) {
    float e = __expf(2.0f * x);            // inf for large x -> 1, ok
    return 1.0f - __fdividef(2.0f, e + 1.0f);
}

// ---- pre-pass: gate-interleave the weights ----
__global__ void permute_weights_kernel(const float* __restrict__ R,
                                       const float* __restrict__ Wx)
{
    const int k = blockIdx.x;      // 0..255
    const int u = threadIdx.x;     // 0..255
    {
        const float* row = R + k * FOURU;
        float4 v = make_float4(row[u], row[UNITSN + u],
                               row[2 * UNITSN + u], row[3 * UNITSN + u]);
        *(float4*)&R_perm[(k * UNITSN + u) * 4] = v;
    }
    if (k < NCHARS) {
        const float* row = Wx + k * FOURU;
        float4 v = make_float4(row[u], row[UNITSN + u],
                               row[2 * UNITSN + u], row[3 * UNITSN + u]);
        *(float4*)&Wx_perm[(k * UNITSN + u) * 4] = v;
    }
}

// Stage one chunk (4 k) of permuted R: 4 x LDG.128.
__device__ __forceinline__ void load_chunk4(
    float4 (&buf)[4], const float4* __restrict__ Rp4, int kc)
{
#pragma unroll
    for (int kk = 0; kk < 4; ++kk)
        buf[kk] = Rp4[(kc * 4 + kk) * UNITSN];
}

// 4 k of the recurrent GEMM: acc2[g][p] += h[k][2p,2p+1] * R[k][u][g].
__device__ __forceinline__ void compute_chunk4(
    unsigned long long (&acc2)[4][BT / 2],
    const float4 (&buf)[4],
    const float (*h_s)[BT],
    int k0)
{
#pragma unroll
    for (int kk = 0; kk < 4; ++kk) {
        const ulonglong2* hp = (const ulonglong2*)(&h_s[k0 + kk][0]);
        ulonglong2 pA = hp[0], pB = hp[1];
        unsigned long long ri = bcast2(buf[kk].x);
        unsigned long long rf = bcast2(buf[kk].y);
        unsigned long long rg = bcast2(buf[kk].z);
        unsigned long long ro = bcast2(buf[kk].w);
        FMA2(acc2[0][0], pA.x, ri); FMA2(acc2[0][1], pA.y, ri);
        FMA2(acc2[0][2], pB.x, ri); FMA2(acc2[0][3], pB.y, ri);
        FMA2(acc2[1][0], pA.x, rf); FMA2(acc2[1][1], pA.y, rf);
        FMA2(acc2[1][2], pB.x, rf); FMA2(acc2[1][3], pB.y, rf);
        FMA2(acc2[2][0], pA.x, rg); FMA2(acc2[2][1], pA.y, rg);
        FMA2(acc2[2][2], pB.x, rg); FMA2(acc2[2][3], pB.y, rg);
        FMA2(acc2[3][0], pA.x, ro); FMA2(acc2[3][1], pA.y, ro);
        FMA2(acc2[3][2], pB.x, ro); FMA2(acc2[3][3], pB.y, ro);
    }
}

__global__ void __launch_bounds__(NTHR, 1) lstm_fused_kernel(
    const int*   __restrict__ inp,
    const float* __restrict__ bias,
    const float* __restrict__ Wd,
    const float* __restrict__ bd,
    float*       __restrict__ out)
{
    __shared__ __align__(16) float h_s[UNITSN][BT];   // 8 KB
    __shared__ unsigned char idx_all[SEQLEN][BT];     // 2 KB

    const int tid = threadIdx.x;          // unit u
    const int b0  = blockIdx.x * BT;

    // Preload all step indices for this CTA (chars < 128 -> bytes).
    for (int i = tid; i < SEQLEN * BT; i += NTHR) {
        int r = i & (BT - 1);
        int t = i >> 3;
        idx_all[t][r] = (unsigned char)inp[(b0 + r) * SEQLEN + t];
    }
    for (int i = tid; i < UNITSN * BT; i += NTHR)
        ((float*)h_s)[i] = 0.0f;

    float c_reg[BT];
#pragma unroll
    for (int r = 0; r < BT; ++r) c_reg[r] = 0.0f;

    unsigned long long bia2[4];
#pragma unroll
    for (int g = 0; g < 4; ++g) bia2[g] = bcast2(bias[g * UNITSN + tid]);

    const float4* Rp4  = (const float4*)R_perm + tid;    // + k*UNITSN per k
    const float4* Wxp4 = (const float4*)Wx_perm + tid;   // + c*UNITSN per char

    // Prime the pipeline (R addresses are step-invariant).
    float4 ra[4], rb[4];
    load_chunk4(ra, Rp4, 0);
    load_chunk4(rb, Rp4, 1);

    for (int t = 0; t < SEQLEN; ++t) {
        __syncthreads();   // h_s writes from step t-1 visible

        unsigned long long acc2[4][BT / 2];
#pragma unroll
        for (int g = 0; g < 4; ++g)
#pragma unroll
            for (int p = 0; p < BT / 2; ++p)
                acc2[g][p] = bia2[g];

        // ---- K loop part 1: chunks 0..23 ----
        for (int kc = 0; kc < 24; kc += 2) {
            compute_chunk4(acc2, ra, h_s, kc * 4);
            load_chunk4(ra, Rp4, (kc + 2) & (NCHUNK - 1));
            compute_chunk4(acc2, rb, h_s, (kc + 1) * 4);
            load_chunk4(rb, Rp4, (kc + 3) & (NCHUNK - 1));
        }

        // Wx gather for this step: 8 x LDG.128 (consumed ~2k cyc later).
        float4 xg[BT];
#pragma unroll
        for (int r = 0; r < BT; ++r)
            xg[r] = Wxp4[(int)idx_all[t][r] * UNITSN];

        // ---- K loop part 2: chunks 24..63; wrap prefetch -> chunks 0,1 of t+1 ----
        for (int kc = 24; kc < NCHUNK; kc += 2) {
            compute_chunk4(acc2, ra, h_s, kc * 4);
            load_chunk4(ra, Rp4, (kc + 2) & (NCHUNK - 1));
            compute_chunk4(acc2, rb, h_s, (kc + 1) * 4);
            load_chunk4(rb, Rp4, (kc + 3) & (NCHUNK - 1));
        }

        // ---- gates + state update ----
        float hv[BT];
#pragma unroll
        for (int p = 0; p < BT / 2; ++p) {
            float zi0, zi1, zf0, zf1, zg0, zg1, zo0, zo1;
            unpack2(acc2[0][p], zi0, zi1);
            unpack2(acc2[1][p], zf0, zf1);
            unpack2(acc2[2][p], zg0, zg1);
            unpack2(acc2[3][p], zo0, zo1);
            zi0 += xg[2 * p].x; zi1 += xg[2 * p + 1].x;
            zf0 += xg[2 * p].y; zf1 += xg[2 * p + 1].y;
            zg0 += xg[2 * p].z; zg1 += xg[2 * p + 1].z;
            zo0 += xg[2 * p].w; zo1 += xg[2 * p + 1].w;
            {
                float i = fast_sigmoid(zi0), f = fast_sigmoid(zf0);
                float g = fast_tanh(zg0),    o = fast_sigmoid(zo0);
                float c = f * c_reg[2 * p] + i * g;
                c_reg[2 * p] = c;
                hv[2 * p] = o * fast_tanh(c);
            }
            {
                float i = fast_sigmoid(zi1), f = fast_sigmoid(zf1);
                float g = fast_tanh(zg1),    o = fast_sigmoid(zo1);
                float c = f * c_reg[2 * p + 1] + i * g;
                c_reg[2 * p + 1] = c;
                hv[2 * p + 1] = o * fast_tanh(c);
            }
        }

        __syncthreads();   // all readers done with h_s for this step
        *(float4*)(&h_s[tid][0]) = make_float4(hv[0], hv[1], hv[2], hv[3]);
        *(float4*)(&h_s[tid][4]) = make_float4(hv[4], hv[5], hv[6], hv[7]);
    }
    __syncthreads();       // final h visible

    // ---- dense + softmax: warp w handles batch row b0+w, lane -> 4 cols ----
    const int w = tid >> 5;
    const int l = tid & 31;

    float4 bb = ((const float4*)bd)[l];
    float a0 = bb.x, a1 = bb.y, a2 = bb.z, a3 = bb.w;
#pragma unroll 4
    for (int u = 0; u < UNITSN; ++u) {
        float hvv = h_s[u][w];                                  // broadcast
        float4 wv = *(const float4*)(Wd + u * NCHARS + 4 * l);  // coalesced
        a0 += hvv * wv.x; a1 += hvv * wv.y;
        a2 += hvv * wv.z; a3 += hvv * wv.w;
    }
    float m = fmaxf(fmaxf(a0, a1), fmaxf(a2, a3));
#pragma unroll
    for (int off = 16; off; off >>= 1)
        m = fmaxf(m, __shfl_xor_sync(0xffffffffu, m, off));
    float e0 = __expf(a0 - m), e1 = __expf(a1 - m);
    float e2 = __expf(a2 - m), e3 = __expf(a3 - m);
    float s = e0 + e1 + e2 + e3;
#pragma unroll
    for (int off = 16; off; off >>= 1)
        s += __shfl_xor_sync(0xffffffffu, s, off);
    float inv = 1.0f / s;
    *(float4*)(out + (b0 + w) * NCHARS + 4 * l) =
        make_float4(e0 * inv, e1 * inv, e2 * inv, e3 * inv);
}

extern "C" void kernel_launch(void* const* d_in, const int* in_sizes, int n_in,
                              void* d_out, int out_size)
{
    const int*   inp  = (const int*)d_in[0];    // [1024, 256]
    const float* Wx   = (const float*)d_in[1];  // [128, 1024]
    const float* R    = (const float*)d_in[2];  // [256, 1024]
    const float* bias = (const float*)d_in[3];  // [1024]
    const float* Wd   = (const float*)d_in[4];  // [256, 128]
    const float* bd   = (const float*)d_in[5];  // [128]
    float*       out  = (float*)d_out;          // [1024, 128]

    permute_weights_kernel<<<UNITSN, NTHR>>>(R, Wx);
    lstm_fused_kernel<<<NCTA, NTHR>>>(inp, bias, Wd, bd, out);
}